// round 5
// baseline (speedup 1.0000x reference)
#include <cuda_runtime.h>
#include <cuda_bf16.h>

#define BATCH 32
#define SEQT  512
#define INP   1024
#define HID   512
#define G     2048          // 4*HID
#define NC    4
#define RNK   8
#define SCALING 2.0f
#define HPAD  516           // HID + 4 floats pad (bank-conflict avoidance)

// -------------------- device scratch (no allocations allowed) --------------------
__device__ float g_weff_ih[(size_t)NC * G * INP];   // 32 MB
__device__ float g_weff_hh[(size_t)NC * G * HID];   // 16 MB
__device__ float g_gx[2ull * BATCH * SEQT * G];     // 268 MB (2 cells of current layer)
__device__ float g_l0out[(size_t)BATCH * SEQT * 2 * HID]; // 64 MB layer-0 output
__device__ float g_hbuf[2][2][BATCH * HID];         // [dir][pingpong]
__device__ unsigned g_bar[2];
__device__ unsigned g_gen[2];

// -------------------- weight folding: W_eff = W + SCALING * Bl @ A --------------------
__global__ void prep_weff_ih(const float* __restrict__ w, const float* __restrict__ a,
                             const float* __restrict__ bl)
{
    size_t idx = (size_t)blockIdx.x * 256 + threadIdx.x;
    const size_t total = (size_t)NC * G * INP;
    if (idx >= total) return;
    int d = (int)(idx % INP);
    int g = (int)((idx / INP) % G);
    int c = (int)(idx / ((size_t)INP * G));
    const float* ar  = a  + (size_t)c * RNK * INP + d;
    const float* blr = bl + ((size_t)c * G + g) * RNK;
    float acc = 0.f;
#pragma unroll
    for (int r = 0; r < RNK; r++) acc += blr[r] * ar[(size_t)r * INP];
    g_weff_ih[idx] = w[idx] + SCALING * acc;
}

__global__ void prep_weff_hh(const float* __restrict__ w, const float* __restrict__ a,
                             const float* __restrict__ bl)
{
    size_t idx = (size_t)blockIdx.x * 256 + threadIdx.x;
    const size_t total = (size_t)NC * G * HID;
    if (idx >= total) return;
    int d = (int)(idx % HID);
    int g = (int)((idx / HID) % G);
    int c = (int)(idx / ((size_t)HID * G));
    const float* ar  = a  + (size_t)c * RNK * HID + d;
    const float* blr = bl + ((size_t)c * G + g) * RNK;
    float acc = 0.f;
#pragma unroll
    for (int r = 0; r < RNK; r++) acc += blr[r] * ar[(size_t)r * HID];
    g_weff_hh[idx] = w[idx] + SCALING * acc;
}

// -------------------- gx GEMM: C[m][n] = sum_k A[m][k]*Weff[n][k] + bias[n] --------------------
// A: (BATCH*SEQT, INP) row-major; Weff: (G, INP) row-major (NT gemm, both K-contiguous)
__global__ __launch_bounds__(256) void gemm_gx(const float* __restrict__ Aext, int layer,
                                               const float* __restrict__ b_ih,
                                               const float* __restrict__ b_hh)
{
    __shared__ float As[16][132];
    __shared__ float Bs[16][132];

    const float* A = layer ? (const float*)g_l0out : Aext;
    const int cellL = blockIdx.z;          // 0/1 = dir within layer
    const int cell  = layer * 2 + cellL;
    const float* W  = g_weff_ih + (size_t)cell * G * INP;

    const int m0 = blockIdx.y * 128;
    const int n0 = blockIdx.x * 128;
    const int tid = threadIdx.x;
    const int tx = tid & 15, ty = tid >> 4;

    float acc[8][8];
#pragma unroll
    for (int i = 0; i < 8; i++)
#pragma unroll
        for (int j = 0; j < 8; j++) acc[i][j] = 0.f;

    for (int k0 = 0; k0 < INP; k0 += 16) {
#pragma unroll
        for (int i = 0; i < 2; i++) {
            int idx = tid + i * 256;
            int row = idx >> 2;
            int c4  = (idx & 3) * 4;
            float4 va = *(const float4*)(A + (size_t)(m0 + row) * INP + k0 + c4);
            As[c4 + 0][row] = va.x; As[c4 + 1][row] = va.y;
            As[c4 + 2][row] = va.z; As[c4 + 3][row] = va.w;
            float4 vb = *(const float4*)(W + (size_t)(n0 + row) * INP + k0 + c4);
            Bs[c4 + 0][row] = vb.x; Bs[c4 + 1][row] = vb.y;
            Bs[c4 + 2][row] = vb.z; Bs[c4 + 3][row] = vb.w;
        }
        __syncthreads();
#pragma unroll
        for (int k = 0; k < 16; k++) {
            float af[8], bf[8];
            *(float4*)(af + 0) = *(const float4*)&As[k][ty * 8];
            *(float4*)(af + 4) = *(const float4*)&As[k][ty * 8 + 4];
            *(float4*)(bf + 0) = *(const float4*)&Bs[k][tx * 8];
            *(float4*)(bf + 4) = *(const float4*)&Bs[k][tx * 8 + 4];
#pragma unroll
            for (int i = 0; i < 8; i++)
#pragma unroll
                for (int j = 0; j < 8; j++)
                    acc[i][j] = fmaf(af[i], bf[j], acc[i][j]);
        }
        __syncthreads();
    }

    float bias[8];
#pragma unroll
    for (int j = 0; j < 8; j++) {
        int n = n0 + tx * 8 + j;
        bias[j] = b_ih[cell * G + n] + b_hh[cell * G + n];
    }
    float* Cb = g_gx + (size_t)cellL * BATCH * SEQT * G;
#pragma unroll
    for (int i = 0; i < 8; i++) {
        float* dst = Cb + (size_t)(m0 + ty * 8 + i) * G + n0 + tx * 8;
        float4 v0 = make_float4(acc[i][0] + bias[0], acc[i][1] + bias[1],
                                acc[i][2] + bias[2], acc[i][3] + bias[3]);
        float4 v1 = make_float4(acc[i][4] + bias[4], acc[i][5] + bias[5],
                                acc[i][6] + bias[6], acc[i][7] + bias[7]);
        ((float4*)dst)[0] = v0;
        ((float4*)dst)[1] = v1;
    }
}

// -------------------- barrier reset --------------------
__global__ void reset_bar()
{
    if (threadIdx.x < 2) { g_bar[threadIdx.x] = 0u; g_gen[threadIdx.x] = 0u; }
}

__device__ __forceinline__ float sigm(float x) { return 1.f / (1.f + __expf(-x)); }

// inline function (NOT a macro) — avoids token substitution of struct field names
__device__ __forceinline__ void dot4(float& acc, const float4 hv, const float4 wv)
{
    acc = fmaf(hv.x, wv.x, fmaf(hv.y, wv.y, fmaf(hv.z, wv.z, fmaf(hv.w, wv.w, acc))));
}

// -------------------- persistent recurrence kernel --------------------
// grid = 128 CTAs: CTA>>6 = direction, CTA&63 selects 8 hidden units.
// smem: W_hh slice (32 gate rows x 512, padded) + h_prev (32 x 512, padded) = 132 KB.
__global__ __launch_bounds__(128, 1) void lstm_rec(int layer, float* __restrict__ dout)
{
    extern __shared__ float sm[];
    float* sW = sm;                 // 32*HPAD
    float* sH = sm + 32 * HPAD;     // 32*HPAD

    const int cta  = blockIdx.x;
    const int dir  = cta >> 6;
    const int cg   = cta & 63;
    const int j0   = cg * 8;
    const int cell = layer * 2 + dir;
    const int tid  = threadIdx.x;

    // Load persistent W_hh_eff slice: row r = gate*8 + u -> weff_hh[cell][gate*HID + j0+u][:]
    {
        const float* wbase = g_weff_hh + (size_t)cell * G * HID;
#pragma unroll
        for (int r = 0; r < 32; r++) {
            int gate = r >> 3, u = r & 7;
            const float4* src = (const float4*)(wbase + (size_t)(gate * HID + j0 + u) * HID);
            ((float4*)(sW + r * HPAD))[tid] = src[tid];
        }
    }
    for (int i = tid; i < 32 * HPAD; i += 128) sH[i] = 0.f;  // h_0 = 0
    __syncthreads();

    const int bp = tid >> 3;
    const int u  = tid & 7;
    const int b0 = bp * 2, b1 = b0 + 1;
    const int j  = j0 + u;
    const float* gx = g_gx + (size_t)dir * BATCH * SEQT * G;
    float* outbuf = layer ? dout : (float*)g_l0out;

    const float4* hp0 = (const float4*)(sH + b0 * HPAD);
    const float4* hp1 = (const float4*)(sH + b1 * HPAD);
    const float4* wvi = (const float4*)(sW + (0  + u) * HPAD);
    const float4* wvf = (const float4*)(sW + (8  + u) * HPAD);
    const float4* wvg = (const float4*)(sW + (16 + u) * HPAD);
    const float4* wvo = (const float4*)(sW + (24 + u) * HPAD);

    float c0 = 0.f, c1 = 0.f, h0v = 0.f, h1v = 0.f;

    for (int s = 0; s < SEQT; s++) {
        const int t = dir ? (SEQT - 1 - s) : s;

        if (s > 0) {
            // stage h(s-1) from the ping-pong global buffer into smem
            const float4* src = (const float4*)&g_hbuf[dir][(s - 1) & 1][0];
            for (int i = tid; i < (BATCH * HID) / 4; i += 128) {
                int bb = i >> 7, kk = i & 127;
                ((float4*)(sH + bb * HPAD))[kk] = src[i];
            }
            __syncthreads();
        }

        float ai0 = 0.f, af0 = 0.f, ag0 = 0.f, ao0 = 0.f;
        float ai1 = 0.f, af1 = 0.f, ag1 = 0.f, ao1 = 0.f;
#pragma unroll 4
        for (int kk = 0; kk < HID / 4; kk++) {
            float4 hv0 = hp0[kk], hv1 = hp1[kk];
            float4 vi = wvi[kk], vf = wvf[kk], vg = wvg[kk], vo = wvo[kk];
            dot4(ai0, hv0, vi); dot4(af0, hv0, vf); dot4(ag0, hv0, vg); dot4(ao0, hv0, vo);
            dot4(ai1, hv1, vi); dot4(af1, hv1, vf); dot4(ag1, hv1, vg); dot4(ao1, hv1, vo);
        }

        size_t gxo0 = ((size_t)(b0 * SEQT + t)) * G + j;
        size_t gxo1 = ((size_t)(b1 * SEQT + t)) * G + j;
        float gi0 = ai0 + gx[gxo0];
        float gf0 = af0 + gx[gxo0 + 512];
        float gg0 = ag0 + gx[gxo0 + 1024];
        float go0 = ao0 + gx[gxo0 + 1536];
        float gi1 = ai1 + gx[gxo1];
        float gf1 = af1 + gx[gxo1 + 512];
        float gg1 = ag1 + gx[gxo1 + 1024];
        float go1 = ao1 + gx[gxo1 + 1536];

        c0  = sigm(gf0) * c0 + sigm(gi0) * tanhf(gg0);
        h0v = sigm(go0) * tanhf(c0);
        c1  = sigm(gf1) * c1 + sigm(gi1) * tanhf(gg1);
        h1v = sigm(go1) * tanhf(c1);

        float* hb = &g_hbuf[dir][s & 1][0];
        hb[b0 * HID + j] = h0v;
        hb[b1 * HID + j] = h1v;
        outbuf[((size_t)b0 * SEQT + t) * (2 * HID) + dir * HID + j] = h0v;
        outbuf[((size_t)b1 * SEQT + t) * (2 * HID) + dir * HID + j] = h1v;

        if (s < SEQT - 1) {
            __syncthreads();                 // all CTA threads done writing h(s)
            if (tid == 0) {
                __threadfence();             // publish our h writes device-wide
                unsigned arr = atomicAdd(&g_bar[dir], 1u);
                if (arr == 63u) {
                    atomicExch(&g_bar[dir], 0u);
                    __threadfence();
                    atomicAdd(&g_gen[dir], 1u);
                } else {
                    unsigned target = (unsigned)(s + 1);
                    while (*((volatile unsigned*)&g_gen[dir]) < target) { }
                    __threadfence();
                }
            }
            __syncthreads();
        }
    }

    // final states: h_n / c_n, cells stacked [layer0d0, layer0d1, layer1d0, layer1d1]
    float* hn = dout + (size_t)BATCH * SEQT * 2 * HID;          // +16777216
    float* cn = hn + (size_t)NC * BATCH * HID;                  // +65536
    size_t o0 = ((size_t)cell * BATCH + b0) * HID + j;
    size_t o1 = ((size_t)cell * BATCH + b1) * HID + j;
    hn[o0] = h0v; hn[o1] = h1v;
    cn[o0] = c0;  cn[o1] = c1;
}

// -------------------- launch --------------------
extern "C" void kernel_launch(void* const* d_in, const int* in_sizes, int n_in,
                              void* d_out, int out_size)
{
    (void)in_sizes; (void)n_in; (void)out_size;
    const float* x     = (const float*)d_in[0];
    const float* w_ih  = (const float*)d_in[1];
    const float* w_hh  = (const float*)d_in[2];
    const float* b_ih  = (const float*)d_in[3];
    const float* b_hh  = (const float*)d_in[4];
    const float* a_ih  = (const float*)d_in[5];
    const float* bl_ih = (const float*)d_in[6];
    const float* a_hh  = (const float*)d_in[7];
    const float* bl_hh = (const float*)d_in[8];
    float* out = (float*)d_out;

    const int SMEM_REC = 64 * HPAD * (int)sizeof(float);  // 132096 B
    cudaFuncSetAttribute(lstm_rec, cudaFuncAttributeMaxDynamicSharedMemorySize, SMEM_REC);

    {
        size_t tih = (size_t)NC * G * INP;
        prep_weff_ih<<<(unsigned)((tih + 255) / 256), 256>>>(w_ih, a_ih, bl_ih);
        size_t thh = (size_t)NC * G * HID;
        prep_weff_hh<<<(unsigned)((thh + 255) / 256), 256>>>(w_hh, a_hh, bl_hh);
    }

    // ---- layer 0 ----
    gemm_gx<<<dim3(16, 128, 2), 256>>>(x, 0, b_ih, b_hh);
    reset_bar<<<1, 32>>>();
    lstm_rec<<<128, 128, SMEM_REC>>>(0, out);

    // ---- layer 1 ----
    gemm_gx<<<dim3(16, 128, 2), 256>>>(nullptr, 1, b_ih, b_hh);
    reset_bar<<<1, 32>>>();
    lstm_rec<<<128, 128, SMEM_REC>>>(1, out);
}

// round 7
// speedup vs baseline: 1.0215x; 1.0215x over previous
#include <cuda_runtime.h>
#include <string.h>

#define BATCH 32
#define SEQT  512
#define INP   1024
#define HID   512
#define G     2048          // 4*HID
#define NC    4
#define RNK   8
#define SCALING 2.0f
#define HPAD  516           // HID + 4 floats pad (recurrence smem row stride)
#define ADS   260           // As_dup row stride (floats): 2*128 + 4, 16B-aligned rows

// -------------------- device scratch (no allocations allowed) --------------------
__device__ float g_weff_ih[(size_t)NC * G * INP];   // 32 MB
__device__ float g_weff_hh[(size_t)NC * G * HID];   // 16 MB
__device__ float g_gx[2ull * BATCH * SEQT * G];     // 268 MB (2 cells of current layer)
__device__ float g_l0out[(size_t)BATCH * SEQT * 2 * HID]; // 64 MB layer-0 output
__device__ float g_hbuf[2][2][BATCH * HID];         // [dir][pingpong]
__device__ unsigned g_bar[2];
__device__ unsigned g_gen[2];

// -------------------- packed f32x2 helpers --------------------
__device__ __forceinline__ unsigned long long ffma2(unsigned long long a,
                                                    unsigned long long b,
                                                    unsigned long long c)
{
    unsigned long long d;
    asm("fma.rn.f32x2 %0, %1, %2, %3;" : "=l"(d) : "l"(a), "l"(b), "l"(c));
    return d;
}
__device__ __forceinline__ float2 upk(unsigned long long v)
{
    float2 f; memcpy(&f, &v, 8); return f;
}
__device__ __forceinline__ float hsum2(unsigned long long a, unsigned long long b)
{
    float2 fa = upk(a), fb = upk(b);
    return (fa.x + fa.y) + (fb.x + fb.y);
}

// -------------------- weight folding: W_eff = W + SCALING * Bl @ A --------------------
__global__ void prep_weff_ih(const float* __restrict__ w, const float* __restrict__ a,
                             const float* __restrict__ bl)
{
    size_t idx = (size_t)blockIdx.x * 256 + threadIdx.x;
    const size_t total = (size_t)NC * G * INP;
    if (idx >= total) return;
    int d = (int)(idx % INP);
    int g = (int)((idx / INP) % G);
    int c = (int)(idx / ((size_t)INP * G));
    const float* ar  = a  + (size_t)c * RNK * INP + d;
    const float* blr = bl + ((size_t)c * G + g) * RNK;
    float acc = 0.f;
#pragma unroll
    for (int r = 0; r < RNK; r++) acc += blr[r] * ar[(size_t)r * INP];
    g_weff_ih[idx] = w[idx] + SCALING * acc;
}

__global__ void prep_weff_hh(const float* __restrict__ w, const float* __restrict__ a,
                             const float* __restrict__ bl)
{
    size_t idx = (size_t)blockIdx.x * 256 + threadIdx.x;
    const size_t total = (size_t)NC * G * HID;
    if (idx >= total) return;
    int d = (int)(idx % HID);
    int g = (int)((idx / HID) % G);
    int c = (int)(idx / ((size_t)HID * G));
    const float* ar  = a  + (size_t)c * RNK * HID + d;
    const float* blr = bl + ((size_t)c * G + g) * RNK;
    float acc = 0.f;
#pragma unroll
    for (int r = 0; r < RNK; r++) acc += blr[r] * ar[(size_t)r * HID];
    g_weff_hh[idx] = w[idx] + SCALING * acc;
}

// -------------------- barrier reset --------------------
__global__ void reset_bar()
{
    if (threadIdx.x < 2) { g_bar[threadIdx.x] = 0u; g_gen[threadIdx.x] = 0u; }
}

// -------------------- gx GEMM (FFMA2): C[m][n] = sum_k A[m][k]*W[n][k] + bias[n] ----
// A: (16384, INP) row-major; Weff: (G, INP) row-major. 128x128x16 tile, 256 thr,
// 8x8 per thread held as 8x4 packed f32x2 (pairs along n). A duplicated in smem.
__global__ __launch_bounds__(256) void gemm_gx(const float* __restrict__ Aext, int layer,
                                               const float* __restrict__ b_ih,
                                               const float* __restrict__ b_hh)
{
    __shared__ float As_dup[16 * ADS];   // [k][2m] duplicated A
    __shared__ float Bs[16 * 132];       // [k][n]

    const float* A = layer ? (const float*)g_l0out : Aext;
    const int cellL = blockIdx.z;
    const int cell  = layer * 2 + cellL;
    const float* W  = g_weff_ih + (size_t)cell * G * INP;

    const int m0 = blockIdx.y * 128;
    const int n0 = blockIdx.x * 128;
    const int tid = threadIdx.x;
    const int tx = tid & 15, ty = tid >> 4;

    // loader mapping: 2 chunks/thread, each chunk = (row, 4 consecutive k)
    const int row0 = tid >> 2,            c40 = (tid & 3) * 4;
    const int row1 = (tid + 256) >> 2,    c41 = ((tid + 256) & 3) * 4;
    const float* Ap0 = A + (size_t)(m0 + row0) * INP + c40;
    const float* Ap1 = A + (size_t)(m0 + row1) * INP + c41;
    const float* Wp0 = W + (size_t)(n0 + row0) * INP + c40;
    const float* Wp1 = W + (size_t)(n0 + row1) * INP + c41;

    unsigned long long acc2[8][4];
#pragma unroll
    for (int i = 0; i < 8; i++)
#pragma unroll
        for (int jp = 0; jp < 4; jp++) acc2[i][jp] = 0ull;

    float4 va0 = *(const float4*)Ap0;
    float4 va1 = *(const float4*)Ap1;
    float4 vb0 = *(const float4*)Wp0;
    float4 vb1 = *(const float4*)Wp1;

    for (int k0 = 0; k0 < INP; k0 += 16) {
        // store current tile: A duplicated as (v,v) float2, B transposed scalar
        {
            float2 d0;
            d0.x = va0.x; d0.y = va0.x; *(float2*)&As_dup[(c40+0)*ADS + 2*row0] = d0;
            d0.x = va0.y; d0.y = va0.y; *(float2*)&As_dup[(c40+1)*ADS + 2*row0] = d0;
            d0.x = va0.z; d0.y = va0.z; *(float2*)&As_dup[(c40+2)*ADS + 2*row0] = d0;
            d0.x = va0.w; d0.y = va0.w; *(float2*)&As_dup[(c40+3)*ADS + 2*row0] = d0;
            d0.x = va1.x; d0.y = va1.x; *(float2*)&As_dup[(c41+0)*ADS + 2*row1] = d0;
            d0.x = va1.y; d0.y = va1.y; *(float2*)&As_dup[(c41+1)*ADS + 2*row1] = d0;
            d0.x = va1.z; d0.y = va1.z; *(float2*)&As_dup[(c41+2)*ADS + 2*row1] = d0;
            d0.x = va1.w; d0.y = va1.w; *(float2*)&As_dup[(c41+3)*ADS + 2*row1] = d0;
            Bs[(c40+0)*132 + row0] = vb0.x; Bs[(c40+1)*132 + row0] = vb0.y;
            Bs[(c40+2)*132 + row0] = vb0.z; Bs[(c40+3)*132 + row0] = vb0.w;
            Bs[(c41+0)*132 + row1] = vb1.x; Bs[(c41+1)*132 + row1] = vb1.y;
            Bs[(c41+2)*132 + row1] = vb1.z; Bs[(c41+3)*132 + row1] = vb1.w;
        }
        __syncthreads();
        if (k0 + 16 < INP) {   // prefetch next tile (hidden under compute)
            va0 = *(const float4*)(Ap0 + k0 + 16);
            va1 = *(const float4*)(Ap1 + k0 + 16);
            vb0 = *(const float4*)(Wp0 + k0 + 16);
            vb1 = *(const float4*)(Wp1 + k0 + 16);
        }
#pragma unroll
        for (int k = 0; k < 16; k++) {
            const ulonglong2* ap = (const ulonglong2*)&As_dup[k * ADS + ty * 16];
            const ulonglong2* bp = (const ulonglong2*)&Bs[k * 132 + tx * 8];
            ulonglong2 a01 = ap[0], a23 = ap[1], a45 = ap[2], a67 = ap[3];
            ulonglong2 bA = bp[0], bB = bp[1];
            unsigned long long apk[8] = {a01.x, a01.y, a23.x, a23.y,
                                         a45.x, a45.y, a67.x, a67.y};
            unsigned long long bpk[4] = {bA.x, bA.y, bB.x, bB.y};
#pragma unroll
            for (int i = 0; i < 8; i++)
#pragma unroll
                for (int jp = 0; jp < 4; jp++)
                    acc2[i][jp] = ffma2(apk[i], bpk[jp], acc2[i][jp]);
        }
        __syncthreads();
    }

    float bias[8];
#pragma unroll
    for (int j = 0; j < 8; j++) {
        int n = n0 + tx * 8 + j;
        bias[j] = b_ih[cell * G + n] + b_hh[cell * G + n];
    }
    float* Cb = g_gx + (size_t)cellL * BATCH * SEQT * G;
#pragma unroll
    for (int i = 0; i < 8; i++) {
        float* dst = Cb + (size_t)(m0 + ty * 8 + i) * G + n0 + tx * 8;
        float2 p0 = upk(acc2[i][0]), p1 = upk(acc2[i][1]);
        float2 p2 = upk(acc2[i][2]), p3 = upk(acc2[i][3]);
        float4 v0 = make_float4(p0.x + bias[0], p0.y + bias[1],
                                p1.x + bias[2], p1.y + bias[3]);
        float4 v1 = make_float4(p2.x + bias[4], p2.y + bias[5],
                                p3.x + bias[6], p3.y + bias[7]);
        ((float4*)dst)[0] = v0;
        ((float4*)dst)[1] = v1;
    }
}

__device__ __forceinline__ float sigm(float x) { return 1.f / (1.f + __expf(-x)); }

// -------------------- persistent recurrence kernel (FFMA2 dots) --------------------
// grid = 128 CTAs: CTA>>6 = direction, CTA&63 -> 8 hidden units. smem = W slice + h.
__global__ __launch_bounds__(128, 1) void lstm_rec(int layer, float* __restrict__ dout)
{
    extern __shared__ float sm[];
    float* sW = sm;                 // 32*HPAD
    float* sH = sm + 32 * HPAD;     // 32*HPAD

    const int cta  = blockIdx.x;
    const int dir  = cta >> 6;
    const int cg   = cta & 63;
    const int j0   = cg * 8;
    const int cell = layer * 2 + dir;
    const int tid  = threadIdx.x;

    {
        const float* wbase = g_weff_hh + (size_t)cell * G * HID;
#pragma unroll
        for (int r = 0; r < 32; r++) {
            int gate = r >> 3, u = r & 7;
            const float4* src = (const float4*)(wbase + (size_t)(gate * HID + j0 + u) * HID);
            ((float4*)(sW + r * HPAD))[tid] = src[tid];
        }
    }
    for (int i = tid; i < 32 * HPAD; i += 128) sH[i] = 0.f;
    __syncthreads();

    const int bp = tid >> 3;
    const int u  = tid & 7;
    const int b0 = bp * 2, b1 = b0 + 1;
    const int j  = j0 + u;
    const float* gx = g_gx + (size_t)dir * BATCH * SEQT * G;
    float* outbuf = layer ? dout : (float*)g_l0out;

    const ulonglong2* hu0 = (const ulonglong2*)(sH + b0 * HPAD);
    const ulonglong2* hu1 = (const ulonglong2*)(sH + b1 * HPAD);
    const ulonglong2* wui = (const ulonglong2*)(sW + (0  + u) * HPAD);
    const ulonglong2* wuf = (const ulonglong2*)(sW + (8  + u) * HPAD);
    const ulonglong2* wug = (const ulonglong2*)(sW + (16 + u) * HPAD);
    const ulonglong2* wuo = (const ulonglong2*)(sW + (24 + u) * HPAD);

    float c0 = 0.f, c1 = 0.f, h0v = 0.f, h1v = 0.f;

    for (int s = 0; s < SEQT; s++) {
        const int t = dir ? (SEQT - 1 - s) : s;

        if (s > 0) {
            const float4* src = (const float4*)&g_hbuf[dir][(s - 1) & 1][0];
            for (int i = tid; i < (BATCH * HID) / 4; i += 128) {
                int bb = i >> 7, kk = i & 127;
                ((float4*)(sH + bb * HPAD))[kk] = src[i];
            }
            __syncthreads();
        }

        // prefetch gx operands (streaming DRAM) before the long dot loop
        size_t gxo0 = ((size_t)(b0 * SEQT + t)) * G + j;
        size_t gxo1 = ((size_t)(b1 * SEQT + t)) * G + j;
        float xi0 = gx[gxo0],        xf0 = gx[gxo0 + 512];
        float xg0 = gx[gxo0 + 1024], xo0 = gx[gxo0 + 1536];
        float xi1 = gx[gxo1],        xf1 = gx[gxo1 + 512];
        float xg1 = gx[gxo1 + 1024], xo1 = gx[gxo1 + 1536];

        // packed accumulators: [gate 0..3=i,f,g,o][batch 0/1][half]
        unsigned long long ac[4][2][2];
#pragma unroll
        for (int gg = 0; gg < 4; gg++)
#pragma unroll
            for (int bb = 0; bb < 2; bb++) { ac[gg][bb][0] = 0ull; ac[gg][bb][1] = 0ull; }

#pragma unroll 4
        for (int kk = 0; kk < HID / 4; kk++) {
            ulonglong2 h0 = hu0[kk], h1 = hu1[kk];
            ulonglong2 vi = wui[kk], vf = wuf[kk], vg = wug[kk], vo = wuo[kk];
            ac[0][0][0] = ffma2(h0.x, vi.x, ac[0][0][0]);
            ac[0][0][1] = ffma2(h0.y, vi.y, ac[0][0][1]);
            ac[1][0][0] = ffma2(h0.x, vf.x, ac[1][0][0]);
            ac[1][0][1] = ffma2(h0.y, vf.y, ac[1][0][1]);
            ac[2][0][0] = ffma2(h0.x, vg.x, ac[2][0][0]);
            ac[2][0][1] = ffma2(h0.y, vg.y, ac[2][0][1]);
            ac[3][0][0] = ffma2(h0.x, vo.x, ac[3][0][0]);
            ac[3][0][1] = ffma2(h0.y, vo.y, ac[3][0][1]);
            ac[0][1][0] = ffma2(h1.x, vi.x, ac[0][1][0]);
            ac[0][1][1] = ffma2(h1.y, vi.y, ac[0][1][1]);
            ac[1][1][0] = ffma2(h1.x, vf.x, ac[1][1][0]);
            ac[1][1][1] = ffma2(h1.y, vf.y, ac[1][1][1]);
            ac[2][1][0] = ffma2(h1.x, vg.x, ac[2][1][0]);
            ac[2][1][1] = ffma2(h1.y, vg.y, ac[2][1][1]);
            ac[3][1][0] = ffma2(h1.x, vo.x, ac[3][1][0]);
            ac[3][1][1] = ffma2(h1.y, vo.y, ac[3][1][1]);
        }

        float gi0 = xi0 + hsum2(ac[0][0][0], ac[0][0][1]);
        float gf0 = xf0 + hsum2(ac[1][0][0], ac[1][0][1]);
        float gg0 = xg0 + hsum2(ac[2][0][0], ac[2][0][1]);
        float go0 = xo0 + hsum2(ac[3][0][0], ac[3][0][1]);
        float gi1 = xi1 + hsum2(ac[0][1][0], ac[0][1][1]);
        float gf1 = xf1 + hsum2(ac[1][1][0], ac[1][1][1]);
        float gg1 = xg1 + hsum2(ac[2][1][0], ac[2][1][1]);
        float go1 = xo1 + hsum2(ac[3][1][0], ac[3][1][1]);

        c0  = sigm(gf0) * c0 + sigm(gi0) * tanhf(gg0);
        h0v = sigm(go0) * tanhf(c0);
        c1  = sigm(gf1) * c1 + sigm(gi1) * tanhf(gg1);
        h1v = sigm(go1) * tanhf(c1);

        float* hb = &g_hbuf[dir][s & 1][0];
        hb[b0 * HID + j] = h0v;
        hb[b1 * HID + j] = h1v;
        outbuf[((size_t)b0 * SEQT + t) * (2 * HID) + dir * HID + j] = h0v;
        outbuf[((size_t)b1 * SEQT + t) * (2 * HID) + dir * HID + j] = h1v;

        if (s < SEQT - 1) {
            __syncthreads();
            if (tid == 0) {
                __threadfence();
                unsigned arr = atomicAdd(&g_bar[dir], 1u);
                if (arr == 63u) {
                    atomicExch(&g_bar[dir], 0u);
                    __threadfence();
                    atomicAdd(&g_gen[dir], 1u);
                } else {
                    unsigned target = (unsigned)(s + 1);
                    while (*((volatile unsigned*)&g_gen[dir]) < target) { }
                    __threadfence();
                }
            }
            __syncthreads();
        }
    }

    float* hn = dout + (size_t)BATCH * SEQT * 2 * HID;
    float* cn = hn + (size_t)NC * BATCH * HID;
    size_t o0 = ((size_t)cell * BATCH + b0) * HID + j;
    size_t o1 = ((size_t)cell * BATCH + b1) * HID + j;
    hn[o0] = h0v; hn[o1] = h1v;
    cn[o0] = c0;  cn[o1] = c1;
}

// -------------------- launch --------------------
extern "C" void kernel_launch(void* const* d_in, const int* in_sizes, int n_in,
                              void* d_out, int out_size)
{
    (void)in_sizes; (void)n_in; (void)out_size;
    const float* x     = (const float*)d_in[0];
    const float* w_ih  = (const float*)d_in[1];
    const float* w_hh  = (const float*)d_in[2];
    const float* b_ih  = (const float*)d_in[3];
    const float* b_hh  = (const float*)d_in[4];
    const float* a_ih  = (const float*)d_in[5];
    const float* bl_ih = (const float*)d_in[6];
    const float* a_hh  = (const float*)d_in[7];
    const float* bl_hh = (const float*)d_in[8];
    float* out = (float*)d_out;

    const int SMEM_REC = 64 * HPAD * (int)sizeof(float);  // 132096 B
    cudaFuncSetAttribute(lstm_rec, cudaFuncAttributeMaxDynamicSharedMemorySize, SMEM_REC);

    {
        size_t tih = (size_t)NC * G * INP;
        prep_weff_ih<<<(unsigned)((tih + 255) / 256), 256>>>(w_ih, a_ih, bl_ih);
        size_t thh = (size_t)NC * G * HID;
        prep_weff_hh<<<(unsigned)((thh + 255) / 256), 256>>>(w_hh, a_hh, bl_hh);
    }

    // ---- layer 0 ----
    gemm_gx<<<dim3(16, 128, 2), 256>>>(x, 0, b_ih, b_hh);
    reset_bar<<<1, 32>>>();
    lstm_rec<<<128, 128, SMEM_REC>>>(0, out);

    // ---- layer 1 ----
    gemm_gx<<<dim3(16, 128, 2), 256>>>(nullptr, 1, b_ih, b_hh);
    reset_bar<<<1, 32>>>();
    lstm_rec<<<128, 128, SMEM_REC>>>(1, out);
}

// round 10
// speedup vs baseline: 1.3281x; 1.3001x over previous
#include <cuda_runtime.h>
#include <cuda_bf16.h>
#include <cstdint>
#include <string.h>

#define BATCH 32
#define SEQT  512
#define INP   1024
#define HID   512
#define G     2048
#define NC    4
#define RNK   8
#define SCALING 2.0f
#define HPAD  516
#define MROWS 16384   // BATCH*SEQT

// -------------------- device scratch (no allocations allowed) --------------------
__device__ __nv_bfloat16 g_wih_hi[(size_t)NC * G * INP];
__device__ __nv_bfloat16 g_wih_lo[(size_t)NC * G * INP];
__device__ float g_weff_hh[(size_t)NC * G * HID];
__device__ __nv_bfloat16 g_xhi[(size_t)MROWS * INP];
__device__ __nv_bfloat16 g_xlo[(size_t)MROWS * INP];
__device__ __nv_bfloat16 g_l1hi[(size_t)MROWS * INP];
__device__ __nv_bfloat16 g_l1lo[(size_t)MROWS * INP];
__device__ float g_gx[2ull * MROWS * G];
__device__ float g_l0out[(size_t)MROWS * 2 * HID];
__device__ float g_hbuf[2][2][BATCH * HID];
__device__ unsigned g_bar[2];
__device__ unsigned g_gen[2];

// -------------------- helpers --------------------
__device__ __forceinline__ uint32_t smem_u32(const void* p)
{
    uint32_t a;
    asm("{ .reg .u64 t; cvta.to.shared.u64 t, %1; cvt.u32.u64 %0, t; }" : "=r"(a) : "l"(p));
    return a;
}
__device__ __forceinline__ void ldsm_x4(uint32_t& r0, uint32_t& r1, uint32_t& r2,
                                        uint32_t& r3, uint32_t addr)
{
    asm volatile("ldmatrix.sync.aligned.m8n8.x4.shared.b16 {%0,%1,%2,%3}, [%4];"
                 : "=r"(r0), "=r"(r1), "=r"(r2), "=r"(r3) : "r"(addr));
}
__device__ __forceinline__ void ldsm_x2(uint32_t& r0, uint32_t& r1, uint32_t addr)
{
    asm volatile("ldmatrix.sync.aligned.m8n8.x2.shared.b16 {%0,%1}, [%2];"
                 : "=r"(r0), "=r"(r1) : "r"(addr));
}
__device__ __forceinline__ void mma16816(float* d, const uint32_t* a, const uint32_t* b)
{
    asm volatile(
        "mma.sync.aligned.m16n8k16.row.col.f32.bf16.bf16.f32 "
        "{%0,%1,%2,%3}, {%4,%5,%6,%7}, {%8,%9}, {%0,%1,%2,%3};"
        : "+f"(d[0]), "+f"(d[1]), "+f"(d[2]), "+f"(d[3])
        : "r"(a[0]), "r"(a[1]), "r"(a[2]), "r"(a[3]), "r"(b[0]), "r"(b[1]));
}
__device__ __forceinline__ void cpasync16(uint32_t saddr, const void* g)
{
    asm volatile("cp.async.cg.shared.global [%0], [%1], 16;"
                 :: "r"(saddr), "l"(__cvta_generic_to_global(g)) : "memory");
}
#define CP_COMMIT() asm volatile("cp.async.commit_group;" ::: "memory")
#define CP_WAIT(n)  asm volatile("cp.async.wait_group %0;" :: "n"(n) : "memory")

__device__ __forceinline__ unsigned long long ffma2(unsigned long long a,
                                                    unsigned long long b,
                                                    unsigned long long c)
{
    unsigned long long d;
    asm("fma.rn.f32x2 %0, %1, %2, %3;" : "=l"(d) : "l"(a), "l"(b), "l"(c));
    return d;
}
__device__ __forceinline__ float2 upk(unsigned long long v) { float2 f; memcpy(&f, &v, 8); return f; }
__device__ __forceinline__ float hsum2(unsigned long long a, unsigned long long b)
{
    float2 fa = upk(a), fb = upk(b);
    return (fa.x + fa.y) + (fb.x + fb.y);
}
__device__ __forceinline__ float sigm(float x) { return 1.f / (1.f + __expf(-x)); }

// -------------------- prep: fold LoRA, bf16-split (ih) / fp32 (hh) --------------------
__global__ void prep_weff_ih(const float* __restrict__ w, const float* __restrict__ a,
                             const float* __restrict__ bl)
{
    size_t idx = (size_t)blockIdx.x * 256 + threadIdx.x;
    const size_t total = (size_t)NC * G * INP;
    if (idx >= total) return;
    int d = (int)(idx % INP);
    int g = (int)((idx / INP) % G);
    int c = (int)(idx / ((size_t)INP * G));
    const float* ar  = a  + (size_t)c * RNK * INP + d;
    const float* blr = bl + ((size_t)c * G + g) * RNK;
    float acc = 0.f;
#pragma unroll
    for (int r = 0; r < RNK; r++) acc += blr[r] * ar[(size_t)r * INP];
    float wv = w[idx] + SCALING * acc;
    __nv_bfloat16 hi = __float2bfloat16(wv);
    g_wih_hi[idx] = hi;
    g_wih_lo[idx] = __float2bfloat16(wv - __bfloat162float(hi));
}

__global__ void prep_weff_hh(const float* __restrict__ w, const float* __restrict__ a,
                             const float* __restrict__ bl)
{
    size_t idx = (size_t)blockIdx.x * 256 + threadIdx.x;
    const size_t total = (size_t)NC * G * HID;
    if (idx >= total) return;
    int d = (int)(idx % HID);
    int g = (int)((idx / HID) % G);
    int c = (int)(idx / ((size_t)HID * G));
    const float* ar  = a  + (size_t)c * RNK * HID + d;
    const float* blr = bl + ((size_t)c * G + g) * RNK;
    float acc = 0.f;
#pragma unroll
    for (int r = 0; r < RNK; r++) acc += blr[r] * ar[(size_t)r * HID];
    g_weff_hh[idx] = w[idx] + SCALING * acc;
}

// -------------------- bf16-split an fp32 activation plane --------------------
__global__ void split_plane(const float* __restrict__ ext, int which)
{
    const float* src = which ? (const float*)g_l0out : ext;
    __nv_bfloat16* hi = which ? g_l1hi : g_xhi;
    __nv_bfloat16* lo = which ? g_l1lo : g_xlo;
    size_t i = ((size_t)blockIdx.x * 256 + threadIdx.x) * 4;
    float4 v = *(const float4*)(src + i);
    __nv_bfloat16 h0 = __float2bfloat16(v.x), h1 = __float2bfloat16(v.y);
    __nv_bfloat16 h2 = __float2bfloat16(v.z), h3 = __float2bfloat16(v.w);
    __nv_bfloat16 l0 = __float2bfloat16(v.x - __bfloat162float(h0));
    __nv_bfloat16 l1 = __float2bfloat16(v.y - __bfloat162float(h1));
    __nv_bfloat16 l2 = __float2bfloat16(v.z - __bfloat162float(h2));
    __nv_bfloat16 l3 = __float2bfloat16(v.w - __bfloat162float(h3));
    __nv_bfloat162* hp = (__nv_bfloat162*)(hi + i);
    __nv_bfloat162* lp = (__nv_bfloat162*)(lo + i);
    hp[0] = __nv_bfloat162(h0, h1); hp[1] = __nv_bfloat162(h2, h3);
    lp[0] = __nv_bfloat162(l0, l1); lp[1] = __nv_bfloat162(l2, l3);
}

__global__ void reset_bar()
{
    if (threadIdx.x < 2) { g_bar[threadIdx.x] = 0u; g_gen[threadIdx.x] = 0u; }
}

// -------------------- tensor-core gx GEMM (mma.sync bf16, fp32 accum) --------------------
// Virtual K=3072 concat: plane0 Ah*Bh, plane1 Ah*Bl, plane2 Al*Bh.
// CTA 128x128, 8 warps (2x4), warp 64x32, K-chunk 32, cp.async double buffer.
#define RS     40                    // smem row stride in bf16 (80 B, conflict-free)
#define ABYTES (128 * RS * 2)        // 10240 B per tile buffer
#define SMEM_GEMM (4 * ABYTES)       // A0,A1,B0,B1 = 40960 B

__global__ __launch_bounds__(256) void gemm_gx_mma(int layer,
                                                   const float* __restrict__ b_ih,
                                                   const float* __restrict__ b_hh)
{
    extern __shared__ __align__(16) char smem[];
    const uint32_t sb = smem_u32(smem);
    const int tid = threadIdx.x, wid = tid >> 5, lane = tid & 31;
    const int wm = wid >> 2, wn = wid & 3;     // warp grid 2(M) x 4(N)
    const int n0 = blockIdx.x * 128, m0 = blockIdx.y * 128, cl = blockIdx.z;
    const int cell = layer * 2 + cl;

    const __nv_bfloat16* Ah = layer ? g_l1hi : g_xhi;
    const __nv_bfloat16* Al = layer ? g_l1lo : g_xlo;
    const __nv_bfloat16* Bh = g_wih_hi + (size_t)cell * G * INP;
    const __nv_bfloat16* Bl = g_wih_lo + (size_t)cell * G * INP;

    float acc[4][4][4];
#pragma unroll
    for (int i = 0; i < 4; i++)
#pragma unroll
        for (int j = 0; j < 4; j++)
#pragma unroll
            for (int q = 0; q < 4; q++) acc[i][j][q] = 0.f;

    const int lrow = tid >> 2, lc8 = (tid & 3) * 8;   // loader: rows lrow, lrow+64

    auto load_chunk = [&](int ch, int buf) {
        const int plane = ch >> 5;
        const int kc = (ch & 31) * 32;
        const __nv_bfloat16* Ap = (plane == 2) ? Al : Ah;
        const __nv_bfloat16* Bp = (plane == 1) ? Bl : Bh;
        uint32_t sa = sb + buf * ABYTES;
        uint32_t sB = sb + 2 * ABYTES + buf * ABYTES;
        cpasync16(sa + (lrow * RS + lc8) * 2,        Ap + (size_t)(m0 + lrow)      * INP + kc + lc8);
        cpasync16(sa + ((lrow + 64) * RS + lc8) * 2, Ap + (size_t)(m0 + lrow + 64) * INP + kc + lc8);
        cpasync16(sB + (lrow * RS + lc8) * 2,        Bp + (size_t)(n0 + lrow)      * INP + kc + lc8);
        cpasync16(sB + ((lrow + 64) * RS + lc8) * 2, Bp + (size_t)(n0 + lrow + 64) * INP + kc + lc8);
        CP_COMMIT();
    };

    // fragment smem offsets (within a buffer), per lane
    const int arow = wm * 64 + (lane & 15);
    const int acol_sel = (lane >> 4) * 8;
    const int brow = wn * 32 + (lane & 7);
    const int bcol_sel = ((lane >> 3) & 1) * 8;

    load_chunk(0, 0);

    for (int ch = 0; ch < 96; ch++) {
        const int b = ch & 1;
        if (ch < 95) load_chunk(ch + 1, 1 - b);
        if (ch < 95) { CP_WAIT(1); } else { CP_WAIT(0); }
        __syncthreads();

        const uint32_t sa = sb + b * ABYTES;
        const uint32_t sB = sb + 2 * ABYTES + b * ABYTES;
#pragma unroll
        for (int ks = 0; ks < 2; ks++) {
            uint32_t afr[4][4], bfr[4][2];
#pragma unroll
            for (int mt = 0; mt < 4; mt++) {
                uint32_t addr = sa + ((arow + mt * 16) * RS + ks * 16 + acol_sel) * 2;
                ldsm_x4(afr[mt][0], afr[mt][1], afr[mt][2], afr[mt][3], addr);
            }
#pragma unroll
            for (int nt = 0; nt < 4; nt++) {
                uint32_t addr = sB + ((brow + nt * 8) * RS + ks * 16 + bcol_sel) * 2;
                ldsm_x2(bfr[nt][0], bfr[nt][1], addr);
            }
#pragma unroll
            for (int mt = 0; mt < 4; mt++)
#pragma unroll
                for (int nt = 0; nt < 4; nt++)
                    mma16816(acc[mt][nt], afr[mt], bfr[nt]);
        }
        __syncthreads();
    }

    // bias + writeback
    float bsum[4][2];
#pragma unroll
    for (int nt = 0; nt < 4; nt++) {
        int col = n0 + wn * 32 + nt * 8 + (lane & 3) * 2;
        bsum[nt][0] = b_ih[(size_t)cell * G + col]     + b_hh[(size_t)cell * G + col];
        bsum[nt][1] = b_ih[(size_t)cell * G + col + 1] + b_hh[(size_t)cell * G + col + 1];
    }
    float* gxbase = g_gx + (size_t)cl * MROWS * G;
#pragma unroll
    for (int mt = 0; mt < 4; mt++) {
        int r0 = m0 + wm * 64 + mt * 16 + (lane >> 2);
        float* row0 = gxbase + (size_t)r0 * G;
        float* row1 = row0 + 8 * (size_t)G;
#pragma unroll
        for (int nt = 0; nt < 4; nt++) {
            int col = n0 + wn * 32 + nt * 8 + (lane & 3) * 2;
            float2 v0 = make_float2(acc[mt][nt][0] + bsum[nt][0],
                                    acc[mt][nt][1] + bsum[nt][1]);
            float2 v1 = make_float2(acc[mt][nt][2] + bsum[nt][0],
                                    acc[mt][nt][3] + bsum[nt][1]);
            *(float2*)(row0 + col) = v0;
            *(float2*)(row1 + col) = v1;
        }
    }
}

// -------------------- persistent recurrence kernel (FFMA2 dots) --------------------
__global__ __launch_bounds__(128, 1) void lstm_rec(int layer, float* __restrict__ dout)
{
    extern __shared__ float sm[];
    float* sW = sm;
    float* sH = sm + 32 * HPAD;

    const int cta  = blockIdx.x;
    const int dir  = cta >> 6;
    const int cg   = cta & 63;
    const int j0   = cg * 8;
    const int cell = layer * 2 + dir;
    const int tid  = threadIdx.x;

    {
        const float* wbase = g_weff_hh + (size_t)cell * G * HID;
#pragma unroll
        for (int r = 0; r < 32; r++) {
            int gate = r >> 3, u = r & 7;
            const float4* src = (const float4*)(wbase + (size_t)(gate * HID + j0 + u) * HID);
            ((float4*)(sW + r * HPAD))[tid] = src[tid];
        }
    }
    for (int i = tid; i < 32 * HPAD; i += 128) sH[i] = 0.f;
    __syncthreads();

    const int bp = tid >> 3;
    const int u  = tid & 7;
    const int b0 = bp * 2, b1 = b0 + 1;
    const int j  = j0 + u;
    const float* gx = g_gx + (size_t)dir * MROWS * G;
    float* outbuf = layer ? dout : (float*)g_l0out;

    const ulonglong2* hu0 = (const ulonglong2*)(sH + b0 * HPAD);
    const ulonglong2* hu1 = (const ulonglong2*)(sH + b1 * HPAD);
    const ulonglong2* wui = (const ulonglong2*)(sW + (0  + u) * HPAD);
    const ulonglong2* wuf = (const ulonglong2*)(sW + (8  + u) * HPAD);
    const ulonglong2* wug = (const ulonglong2*)(sW + (16 + u) * HPAD);
    const ulonglong2* wuo = (const ulonglong2*)(sW + (24 + u) * HPAD);

    float c0 = 0.f, c1 = 0.f, h0v = 0.f, h1v = 0.f;

    for (int s = 0; s < SEQT; s++) {
        const int t = dir ? (SEQT - 1 - s) : s;

        if (s > 0) {
            const float4* src = (const float4*)&g_hbuf[dir][(s - 1) & 1][0];
            for (int i = tid; i < (BATCH * HID) / 4; i += 128) {
                int bb = i >> 7, kk = i & 127;
                ((float4*)(sH + bb * HPAD))[kk] = src[i];
            }
            __syncthreads();
        }

        size_t gxo0 = ((size_t)(b0 * SEQT + t)) * G + j;
        size_t gxo1 = ((size_t)(b1 * SEQT + t)) * G + j;
        float xi0 = gx[gxo0],        xf0 = gx[gxo0 + 512];
        float xg0 = gx[gxo0 + 1024], xo0 = gx[gxo0 + 1536];
        float xi1 = gx[gxo1],        xf1 = gx[gxo1 + 512];
        float xg1 = gx[gxo1 + 1024], xo1 = gx[gxo1 + 1536];

        unsigned long long ac[4][2][2];
#pragma unroll
        for (int gg = 0; gg < 4; gg++)
#pragma unroll
            for (int bb = 0; bb < 2; bb++) { ac[gg][bb][0] = 0ull; ac[gg][bb][1] = 0ull; }

#pragma unroll 4
        for (int kk = 0; kk < HID / 4; kk++) {
            ulonglong2 h0 = hu0[kk], h1 = hu1[kk];
            ulonglong2 vi = wui[kk], vf = wuf[kk], vg = wug[kk], vo = wuo[kk];
            ac[0][0][0] = ffma2(h0.x, vi.x, ac[0][0][0]);
            ac[0][0][1] = ffma2(h0.y, vi.y, ac[0][0][1]);
            ac[1][0][0] = ffma2(h0.x, vf.x, ac[1][0][0]);
            ac[1][0][1] = ffma2(h0.y, vf.y, ac[1][0][1]);
            ac[2][0][0] = ffma2(h0.x, vg.x, ac[2][0][0]);
            ac[2][0][1] = ffma2(h0.y, vg.y, ac[2][0][1]);
            ac[3][0][0] = ffma2(h0.x, vo.x, ac[3][0][0]);
            ac[3][0][1] = ffma2(h0.y, vo.y, ac[3][0][1]);
            ac[0][1][0] = ffma2(h1.x, vi.x, ac[0][1][0]);
            ac[0][1][1] = ffma2(h1.y, vi.y, ac[0][1][1]);
            ac[1][1][0] = ffma2(h1.x, vf.x, ac[1][1][0]);
            ac[1][1][1] = ffma2(h1.y, vf.y, ac[1][1][1]);
            ac[2][1][0] = ffma2(h1.x, vg.x, ac[2][1][0]);
            ac[2][1][1] = ffma2(h1.y, vg.y, ac[2][1][1]);
            ac[3][1][0] = ffma2(h1.x, vo.x, ac[3][1][0]);
            ac[3][1][1] = ffma2(h1.y, vo.y, ac[3][1][1]);
        }

        float gi0 = xi0 + hsum2(ac[0][0][0], ac[0][0][1]);
        float gf0 = xf0 + hsum2(ac[1][0][0], ac[1][0][1]);
        float gg0 = xg0 + hsum2(ac[2][0][0], ac[2][0][1]);
        float go0 = xo0 + hsum2(ac[3][0][0], ac[3][0][1]);
        float gi1 = xi1 + hsum2(ac[0][1][0], ac[0][1][1]);
        float gf1 = xf1 + hsum2(ac[1][1][0], ac[1][1][1]);
        float gg1 = xg1 + hsum2(ac[2][1][0], ac[2][1][1]);
        float go1 = xo1 + hsum2(ac[3][1][0], ac[3][1][1]);

        c0  = sigm(gf0) * c0 + sigm(gi0) * tanhf(gg0);
        h0v = sigm(go0) * tanhf(c0);
        c1  = sigm(gf1) * c1 + sigm(gi1) * tanhf(gg1);
        h1v = sigm(go1) * tanhf(c1);

        float* hb = &g_hbuf[dir][s & 1][0];
        hb[b0 * HID + j] = h0v;
        hb[b1 * HID + j] = h1v;
        outbuf[((size_t)b0 * SEQT + t) * (2 * HID) + dir * HID + j] = h0v;
        outbuf[((size_t)b1 * SEQT + t) * (2 * HID) + dir * HID + j] = h1v;

        if (s < SEQT - 1) {
            __syncthreads();
            if (tid == 0) {
                __threadfence();
                unsigned arr = atomicAdd(&g_bar[dir], 1u);
                if (arr == 63u) {
                    atomicExch(&g_bar[dir], 0u);
                    __threadfence();
                    atomicAdd(&g_gen[dir], 1u);
                } else {
                    unsigned target = (unsigned)(s + 1);
                    while (*((volatile unsigned*)&g_gen[dir]) < target) { }
                    __threadfence();
                }
            }
            __syncthreads();
        }
    }

    float* hn = dout + (size_t)MROWS * 2 * HID;
    float* cn = hn + (size_t)NC * BATCH * HID;
    size_t o0 = ((size_t)cell * BATCH + b0) * HID + j;
    size_t o1 = ((size_t)cell * BATCH + b1) * HID + j;
    hn[o0] = h0v; hn[o1] = h1v;
    cn[o0] = c0;  cn[o1] = c1;
}

// -------------------- launch --------------------
extern "C" void kernel_launch(void* const* d_in, const int* in_sizes, int n_in,
                              void* d_out, int out_size)
{
    (void)in_sizes; (void)n_in; (void)out_size;
    const float* x     = (const float*)d_in[0];
    const float* w_ih  = (const float*)d_in[1];
    const float* w_hh  = (const float*)d_in[2];
    const float* b_ih  = (const float*)d_in[3];
    const float* b_hh  = (const float*)d_in[4];
    const float* a_ih  = (const float*)d_in[5];
    const float* bl_ih = (const float*)d_in[6];
    const float* a_hh  = (const float*)d_in[7];
    const float* bl_hh = (const float*)d_in[8];
    float* out = (float*)d_out;

    const int SMEM_REC = 64 * HPAD * (int)sizeof(float);  // 132096 B
    cudaFuncSetAttribute(lstm_rec, cudaFuncAttributeMaxDynamicSharedMemorySize, SMEM_REC);
    cudaFuncSetAttribute(gemm_gx_mma, cudaFuncAttributeMaxDynamicSharedMemorySize, SMEM_GEMM);

    size_t tih = (size_t)NC * G * INP;
    prep_weff_ih<<<(unsigned)((tih + 255) / 256), 256>>>(w_ih, a_ih, bl_ih);   // 0
    size_t thh = (size_t)NC * G * HID;
    prep_weff_hh<<<(unsigned)((thh + 255) / 256), 256>>>(w_hh, a_hh, bl_hh);   // 1
    split_plane<<<(unsigned)((size_t)MROWS * INP / 1024), 256>>>(x, 0);        // 2
    reset_bar<<<1, 32>>>();                                                    // 3

    // ---- layer 0 ----
    gemm_gx_mma<<<dim3(16, 128, 2), 256, SMEM_GEMM>>>(0, b_ih, b_hh);          // 4
    lstm_rec<<<128, 128, SMEM_REC>>>(0, out);                                  // 5 (ncu -s 5)

    // ---- layer 1 ----
    split_plane<<<(unsigned)((size_t)MROWS * INP / 1024), 256>>>(nullptr, 1);  // 6
    reset_bar<<<1, 32>>>();                                                    // 7
    gemm_gx_mma<<<dim3(16, 128, 2), 256, SMEM_GEMM>>>(1, b_ih, b_hh);          // 8
    lstm_rec<<<128, 128, SMEM_REC>>>(1, out);                                  // 9
}

// round 12
// speedup vs baseline: 2.0232x; 1.5233x over previous
#include <cuda_runtime.h>
#include <cuda_bf16.h>
#include <cstdint>
#include <string.h>

#define BATCH 32
#define SEQT  512
#define INP   1024
#define HID   512
#define G     2048
#define NC    4
#define RNK   8
#define SCALING 2.0f
#define MROWS 16384   // BATCH*SEQT

// -------------------- device scratch (no allocations allowed) --------------------
__device__ __nv_bfloat16 g_wih_hi[(size_t)NC * G * INP];
__device__ __nv_bfloat16 g_wih_lo[(size_t)NC * G * INP];
__device__ __nv_bfloat16 g_whh_hi[(size_t)NC * G * HID];
__device__ __nv_bfloat16 g_whh_lo[(size_t)NC * G * HID];
__device__ __nv_bfloat16 g_xhi[(size_t)MROWS * INP];
__device__ __nv_bfloat16 g_xlo[(size_t)MROWS * INP];
__device__ __nv_bfloat16 g_l1hi[(size_t)MROWS * INP];
__device__ __nv_bfloat16 g_l1lo[(size_t)MROWS * INP];
__device__ float g_gx[2ull * MROWS * G];
__device__ __nv_bfloat16 g_hb16[2][2][2][BATCH * HID];  // [dir][pingpong][plane hi/lo]
__device__ unsigned g_bar[2];
__device__ unsigned g_gen[2];

// -------------------- helpers --------------------
__device__ __forceinline__ uint32_t smem_u32(const void* p)
{
    uint32_t a;
    asm("{ .reg .u64 t; cvta.to.shared.u64 t, %1; cvt.u32.u64 %0, t; }" : "=r"(a) : "l"(p));
    return a;
}
__device__ __forceinline__ void ldsm_x4(uint32_t& r0, uint32_t& r1, uint32_t& r2,
                                        uint32_t& r3, uint32_t addr)
{
    asm volatile("ldmatrix.sync.aligned.m8n8.x4.shared.b16 {%0,%1,%2,%3}, [%4];"
                 : "=r"(r0), "=r"(r1), "=r"(r2), "=r"(r3) : "r"(addr));
}
__device__ __forceinline__ void ldsm_x2(uint32_t& r0, uint32_t& r1, uint32_t addr)
{
    asm volatile("ldmatrix.sync.aligned.m8n8.x2.shared.b16 {%0,%1}, [%2];"
                 : "=r"(r0), "=r"(r1) : "r"(addr));
}
__device__ __forceinline__ void mma16816(float* d, const uint32_t* a, const uint32_t* b)
{
    asm volatile(
        "mma.sync.aligned.m16n8k16.row.col.f32.bf16.bf16.f32 "
        "{%0,%1,%2,%3}, {%4,%5,%6,%7}, {%8,%9}, {%0,%1,%2,%3};"
        : "+f"(d[0]), "+f"(d[1]), "+f"(d[2]), "+f"(d[3])
        : "r"(a[0]), "r"(a[1]), "r"(a[2]), "r"(a[3]), "r"(b[0]), "r"(b[1]));
}
__device__ __forceinline__ void cpasync16(uint32_t saddr, const void* g)
{
    asm volatile("cp.async.cg.shared.global [%0], [%1], 16;"
                 :: "r"(saddr), "l"(__cvta_generic_to_global(g)) : "memory");
}
#define CP_COMMIT() asm volatile("cp.async.commit_group;" ::: "memory")
#define CP_WAIT(n)  asm volatile("cp.async.wait_group %0;" :: "n"(n) : "memory")

__device__ __forceinline__ float sigm(float x) { return 1.f / (1.f + __expf(-x)); }

// -------------------- prep: fold LoRA + bf16-split --------------------
__global__ void prep_weff_ih(const float* __restrict__ w, const float* __restrict__ a,
                             const float* __restrict__ bl)
{
    size_t idx = (size_t)blockIdx.x * 256 + threadIdx.x;
    const size_t total = (size_t)NC * G * INP;
    if (idx >= total) return;
    int d = (int)(idx % INP);
    int g = (int)((idx / INP) % G);
    int c = (int)(idx / ((size_t)INP * G));
    const float* ar  = a  + (size_t)c * RNK * INP + d;
    const float* blr = bl + ((size_t)c * G + g) * RNK;
    float acc = 0.f;
#pragma unroll
    for (int r = 0; r < RNK; r++) acc += blr[r] * ar[(size_t)r * INP];
    float wv = w[idx] + SCALING * acc;
    __nv_bfloat16 hi = __float2bfloat16(wv);
    g_wih_hi[idx] = hi;
    g_wih_lo[idx] = __float2bfloat16(wv - __bfloat162float(hi));
}

__global__ void prep_weff_hh(const float* __restrict__ w, const float* __restrict__ a,
                             const float* __restrict__ bl)
{
    size_t idx = (size_t)blockIdx.x * 256 + threadIdx.x;
    const size_t total = (size_t)NC * G * HID;
    if (idx >= total) return;
    int d = (int)(idx % HID);
    int g = (int)((idx / HID) % G);
    int c = (int)(idx / ((size_t)HID * G));
    const float* ar  = a  + (size_t)c * RNK * HID + d;
    const float* blr = bl + ((size_t)c * G + g) * RNK;
    float acc = 0.f;
#pragma unroll
    for (int r = 0; r < RNK; r++) acc += blr[r] * ar[(size_t)r * HID];
    float wv = w[idx] + SCALING * acc;
    __nv_bfloat16 hi = __float2bfloat16(wv);
    g_whh_hi[idx] = hi;
    g_whh_lo[idx] = __float2bfloat16(wv - __bfloat162float(hi));
}

// -------------------- bf16-split x --------------------
__global__ void split_x(const float* __restrict__ src)
{
    size_t i = ((size_t)blockIdx.x * 256 + threadIdx.x) * 4;
    float4 v = *(const float4*)(src + i);
    __nv_bfloat16 h0 = __float2bfloat16(v.x), h1 = __float2bfloat16(v.y);
    __nv_bfloat16 h2 = __float2bfloat16(v.z), h3 = __float2bfloat16(v.w);
    __nv_bfloat16 l0 = __float2bfloat16(v.x - __bfloat162float(h0));
    __nv_bfloat16 l1 = __float2bfloat16(v.y - __bfloat162float(h1));
    __nv_bfloat16 l2 = __float2bfloat16(v.z - __bfloat162float(h2));
    __nv_bfloat16 l3 = __float2bfloat16(v.w - __bfloat162float(h3));
    __nv_bfloat162* hp = (__nv_bfloat162*)(g_xhi + i);
    __nv_bfloat162* lp = (__nv_bfloat162*)(g_xlo + i);
    hp[0] = __nv_bfloat162(h0, h1); hp[1] = __nv_bfloat162(h2, h3);
    lp[0] = __nv_bfloat162(l0, l1); lp[1] = __nv_bfloat162(l2, l3);
}

__global__ void reset_bar()
{
    if (threadIdx.x < 2) { g_bar[threadIdx.x] = 0u; g_gen[threadIdx.x] = 0u; }
}

// -------------------- tensor-core gx GEMM (unchanged from passing R10) --------------------
#define RS     40
#define ABYTES (128 * RS * 2)
#define SMEM_GEMM (4 * ABYTES)

__global__ __launch_bounds__(256) void gemm_gx_mma(int layer,
                                                   const float* __restrict__ b_ih,
                                                   const float* __restrict__ b_hh)
{
    extern __shared__ __align__(16) char smem[];
    const uint32_t sb = smem_u32(smem);
    const int tid = threadIdx.x, wid = tid >> 5, lane = tid & 31;
    const int wm = wid >> 2, wn = wid & 3;
    const int n0 = blockIdx.x * 128, m0 = blockIdx.y * 128, cl = blockIdx.z;
    const int cell = layer * 2 + cl;

    const __nv_bfloat16* Ah = layer ? g_l1hi : g_xhi;
    const __nv_bfloat16* Al = layer ? g_l1lo : g_xlo;
    const __nv_bfloat16* Bh = g_wih_hi + (size_t)cell * G * INP;
    const __nv_bfloat16* Bl = g_wih_lo + (size_t)cell * G * INP;

    float acc[4][4][4];
#pragma unroll
    for (int i = 0; i < 4; i++)
#pragma unroll
        for (int j = 0; j < 4; j++)
#pragma unroll
            for (int q = 0; q < 4; q++) acc[i][j][q] = 0.f;

    const int lrow = tid >> 2, lc8 = (tid & 3) * 8;

    auto load_chunk = [&](int ch, int buf) {
        const int plane = ch >> 5;
        const int kc = (ch & 31) * 32;
        const __nv_bfloat16* Ap = (plane == 2) ? Al : Ah;
        const __nv_bfloat16* Bp = (plane == 1) ? Bl : Bh;
        uint32_t sa = sb + buf * ABYTES;
        uint32_t sB = sb + 2 * ABYTES + buf * ABYTES;
        cpasync16(sa + (lrow * RS + lc8) * 2,        Ap + (size_t)(m0 + lrow)      * INP + kc + lc8);
        cpasync16(sa + ((lrow + 64) * RS + lc8) * 2, Ap + (size_t)(m0 + lrow + 64) * INP + kc + lc8);
        cpasync16(sB + (lrow * RS + lc8) * 2,        Bp + (size_t)(n0 + lrow)      * INP + kc + lc8);
        cpasync16(sB + ((lrow + 64) * RS + lc8) * 2, Bp + (size_t)(n0 + lrow + 64) * INP + kc + lc8);
        CP_COMMIT();
    };

    const int arow = wm * 64 + (lane & 15);
    const int acol_sel = (lane >> 4) * 8;
    const int brow = wn * 32 + (lane & 7);
    const int bcol_sel = ((lane >> 3) & 1) * 8;

    load_chunk(0, 0);

    for (int ch = 0; ch < 96; ch++) {
        const int b = ch & 1;
        if (ch < 95) load_chunk(ch + 1, 1 - b);
        if (ch < 95) { CP_WAIT(1); } else { CP_WAIT(0); }
        __syncthreads();

        const uint32_t sa = sb + b * ABYTES;
        const uint32_t sB = sb + 2 * ABYTES + b * ABYTES;
#pragma unroll
        for (int ks = 0; ks < 2; ks++) {
            uint32_t afr[4][4], bfr[4][2];
#pragma unroll
            for (int mt = 0; mt < 4; mt++) {
                uint32_t addr = sa + ((arow + mt * 16) * RS + ks * 16 + acol_sel) * 2;
                ldsm_x4(afr[mt][0], afr[mt][1], afr[mt][2], afr[mt][3], addr);
            }
#pragma unroll
            for (int nt = 0; nt < 4; nt++) {
                uint32_t addr = sB + ((brow + nt * 8) * RS + ks * 16 + bcol_sel) * 2;
                ldsm_x2(bfr[nt][0], bfr[nt][1], addr);
            }
#pragma unroll
            for (int mt = 0; mt < 4; mt++)
#pragma unroll
                for (int nt = 0; nt < 4; nt++)
                    mma16816(acc[mt][nt], afr[mt], bfr[nt]);
        }
        __syncthreads();
    }

    float bsum[4][2];
#pragma unroll
    for (int nt = 0; nt < 4; nt++) {
        int col = n0 + wn * 32 + nt * 8 + (lane & 3) * 2;
        bsum[nt][0] = b_ih[(size_t)cell * G + col]     + b_hh[(size_t)cell * G + col];
        bsum[nt][1] = b_ih[(size_t)cell * G + col + 1] + b_hh[(size_t)cell * G + col + 1];
    }
    float* gxbase = g_gx + (size_t)cl * MROWS * G;
#pragma unroll
    for (int mt = 0; mt < 4; mt++) {
        int r0 = m0 + wm * 64 + mt * 16 + (lane >> 2);
        float* row0 = gxbase + (size_t)r0 * G;
        float* row1 = row0 + 8 * (size_t)G;
#pragma unroll
        for (int nt = 0; nt < 4; nt++) {
            int col = n0 + wn * 32 + nt * 8 + (lane & 3) * 2;
            float2 v0 = make_float2(acc[mt][nt][0] + bsum[nt][0],
                                    acc[mt][nt][1] + bsum[nt][1]);
            float2 v1 = make_float2(acc[mt][nt][2] + bsum[nt][0],
                                    acc[mt][nt][3] + bsum[nt][1]);
            *(float2*)(row0 + col) = v0;
            *(float2*)(row1 + col) = v1;
        }
    }
}

// -------------------- persistent recurrence (mma.sync h@W) --------------------
// 128 CTAs: dir = cta>>6, 8 hidden units each. smem: h hi/lo + W hi/lo (520-stride
// bf16 rows) + P tile. W rows reordered: smem row R -> gate=(R&7)>>1,
// unit = j0 + 2*(R>>3) + (R&1). Warp w owns n-tile rows [8w, 8w+8) = units 2w,2w+1.
#define HROW 1040                 // bytes per smem row (520 bf16)
#define SH0  0
#define SH1  (SH0 + 32 * HROW)    // 33280
#define SW0  (SH1 + 32 * HROW)
#define SW1  (SW0 + 32 * HROW)
#define SP   (SW1 + 32 * HROW)    // 133120
#define PST  34                   // P stride (floats)
#define SMEM_REC (SP + 32 * PST * 4 + 128)

__global__ __launch_bounds__(128, 1) void lstm_rec(int layer, float* __restrict__ dout)
{
    extern __shared__ __align__(16) char smc[];
    const uint32_t sb = smem_u32(smc);
    float* Pt = (float*)(smc + SP);

    const int cta  = blockIdx.x;
    const int dir  = cta >> 6;
    const int j0   = (cta & 63) * 8;
    const int cell = layer * 2 + dir;
    const int tid  = threadIdx.x;
    const int wid  = tid >> 5, lane = tid & 31;

    // load W slice (both planes), reordered rows, 520-stride
    {
        const __nv_bfloat16* srcs[2] = { g_whh_hi + (size_t)cell * G * HID,
                                         g_whh_lo + (size_t)cell * G * HID };
        const uint32_t dsts[2] = { SW0, SW1 };
#pragma unroll
        for (int p = 0; p < 2; p++) {
            for (int i = tid; i < 2048; i += 128) {
                int R = i >> 6, k8 = (i & 63) * 8;
                int gate = (R & 7) >> 1;
                int urow = 2 * (R >> 3) + (R & 1);
                const uint4 v = *(const uint4*)(srcs[p] + (size_t)(gate * HID + j0 + urow) * HID + k8);
                *(uint4*)(smc + dsts[p] + R * HROW + k8 * 2) = v;
            }
        }
    }
    // zero h smem (both planes, incl. padding)
    for (int i = tid; i < (2 * 32 * HROW) / 4; i += 128) ((uint32_t*)(smc + SH0))[i] = 0u;
    __syncthreads();

    // fragment addressing (same pattern as the validated GEMM)
    const uint32_t aoff = (uint32_t)((lane & 15) * HROW + (lane >> 4) * 16);
    const uint32_t boff = (uint32_t)(wid * 8 * HROW + (lane & 7) * HROW + ((lane >> 3) & 1) * 16);
    const uint32_t ah_b = sb + SH0 + aoff, al_b = sb + SH1 + aoff;
    const uint32_t bh_b = sb + SW0 + boff, bl_b = sb + SW1 + boff;

    const int bp = tid >> 3;          // batch pair 0..15
    const int u  = tid & 7;
    const int b0 = bp * 2, b1 = b0 + 1;
    const int j  = j0 + u;
    const int Rg0 = (u >> 1) * 8 + (u & 1);   // P column for gate g: Rg0 + 2g
    const float* gx = g_gx + (size_t)dir * MROWS * G;

    float c0 = 0.f, c1 = 0.f, h0v = 0.f, h1v = 0.f;

    for (int s = 0; s < SEQT; s++) {
        const int t = dir ? (SEQT - 1 - s) : s;

        if (s > 0) {   // stage h(s-1) bf16 planes into smem
            const __nv_bfloat16* s0 = g_hb16[dir][(s - 1) & 1][0];
            const __nv_bfloat16* s1 = g_hb16[dir][(s - 1) & 1][1];
            for (int i = tid; i < 2048; i += 128) {
                int b = i >> 6, k8 = (i & 63) * 8;
                *(uint4*)(smc + SH0 + b * HROW + k8 * 2) = *(const uint4*)(s0 + b * HID + k8);
                *(uint4*)(smc + SH1 + b * HROW + k8 * 2) = *(const uint4*)(s1 + b * HID + k8);
            }
            __syncthreads();
        }

        // prefetch gx operands
        size_t gxo0 = ((size_t)(b0 * SEQT + t)) * G + j;
        size_t gxo1 = ((size_t)(b1 * SEQT + t)) * G + j;
        float xi0 = gx[gxo0],        xf0 = gx[gxo0 + 512];
        float xg0 = gx[gxo0 + 1024], xo0 = gx[gxo0 + 1536];
        float xi1 = gx[gxo1],        xf1 = gx[gxo1 + 512];
        float xg1 = gx[gxo1 + 1024], xo1 = gx[gxo1 + 1536];

        // mma: P = Hhi*Whi + Hhi*Wlo + Hlo*Whi
        float acc[2][4];
#pragma unroll
        for (int m = 0; m < 2; m++)
#pragma unroll
            for (int q = 0; q < 4; q++) acc[m][q] = 0.f;

#pragma unroll 4
        for (int kt = 0; kt < 32; kt++) {
            const uint32_t kb = kt * 32;
            uint32_t ah0[4], ah1[4], al0[4], al1[4], bh[2], bl[2];
            ldsm_x4(ah0[0], ah0[1], ah0[2], ah0[3], ah_b + kb);
            ldsm_x4(ah1[0], ah1[1], ah1[2], ah1[3], ah_b + 16 * HROW + kb);
            ldsm_x4(al0[0], al0[1], al0[2], al0[3], al_b + kb);
            ldsm_x4(al1[0], al1[1], al1[2], al1[3], al_b + 16 * HROW + kb);
            ldsm_x2(bh[0], bh[1], bh_b + kb);
            ldsm_x2(bl[0], bl[1], bl_b + kb);
            mma16816(acc[0], ah0, bh);
            mma16816(acc[0], ah0, bl);
            mma16816(acc[0], al0, bh);
            mma16816(acc[1], ah1, bh);
            mma16816(acc[1], ah1, bl);
            mma16816(acc[1], al1, bh);
        }

        // accumulators -> P smem tile
        {
            int prow = lane >> 2;
            int pcol = wid * 8 + 2 * (lane & 3);
#pragma unroll
            for (int m = 0; m < 2; m++) {
                int bb = prow + m * 16;
                *(float2*)&Pt[bb * PST + pcol]       = make_float2(acc[m][0], acc[m][1]);
                *(float2*)&Pt[(bb + 8) * PST + pcol] = make_float2(acc[m][2], acc[m][3]);
            }
        }
        __syncthreads();

        // pointwise epilogue: thread = (2 batches, 1 unit)
        float gi0 = xi0 + Pt[b0 * PST + Rg0 + 0];
        float gf0 = xf0 + Pt[b0 * PST + Rg0 + 2];
        float gg0 = xg0 + Pt[b0 * PST + Rg0 + 4];
        float go0 = xo0 + Pt[b0 * PST + Rg0 + 6];
        float gi1 = xi1 + Pt[b1 * PST + Rg0 + 0];
        float gf1 = xf1 + Pt[b1 * PST + Rg0 + 2];
        float gg1 = xg1 + Pt[b1 * PST + Rg0 + 4];
        float go1 = xo1 + Pt[b1 * PST + Rg0 + 6];

        c0  = sigm(gf0) * c0 + sigm(gi0) * tanhf(gg0);
        h0v = sigm(go0) * tanhf(c0);
        c1  = sigm(gf1) * c1 + sigm(gi1) * tanhf(gg1);
        h1v = sigm(go1) * tanhf(c1);

        // publish h: bf16 hi/lo for the ring, plus layer-specific output
        __nv_bfloat16 hh0 = __float2bfloat16(h0v);
        __nv_bfloat16 hl0 = __float2bfloat16(h0v - __bfloat162float(hh0));
        __nv_bfloat16 hh1 = __float2bfloat16(h1v);
        __nv_bfloat16 hl1 = __float2bfloat16(h1v - __bfloat162float(hh1));
        g_hb16[dir][s & 1][0][b0 * HID + j] = hh0;
        g_hb16[dir][s & 1][1][b0 * HID + j] = hl0;
        g_hb16[dir][s & 1][0][b1 * HID + j] = hh1;
        g_hb16[dir][s & 1][1][b1 * HID + j] = hl1;
        if (layer == 0) {
            size_t r0o = ((size_t)(b0 * SEQT + t)) * INP + dir * HID + j;
            size_t r1o = ((size_t)(b1 * SEQT + t)) * INP + dir * HID + j;
            g_l1hi[r0o] = hh0; g_l1lo[r0o] = hl0;
            g_l1hi[r1o] = hh1; g_l1lo[r1o] = hl1;
        } else {
            dout[((size_t)b0 * SEQT + t) * (2 * HID) + dir * HID + j] = h0v;
            dout[((size_t)b1 * SEQT + t) * (2 * HID) + dir * HID + j] = h1v;
        }

        if (s < SEQT - 1) {
            __syncthreads();
            if (tid == 0) {
                __threadfence();
                unsigned arr = atomicAdd(&g_bar[dir], 1u);
                if (arr == 63u) {
                    atomicExch(&g_bar[dir], 0u);
                    __threadfence();
                    atomicAdd(&g_gen[dir], 1u);
                } else {
                    unsigned target = (unsigned)(layer * (SEQT - 1) + s + 1);
                    while (*((volatile unsigned*)&g_gen[dir]) < target) { }
                    __threadfence();
                }
            }
            __syncthreads();
        }
    }

    float* hn = dout + (size_t)MROWS * 2 * HID;
    float* cn = hn + (size_t)NC * BATCH * HID;
    size_t o0 = ((size_t)cell * BATCH + b0) * HID + j;
    size_t o1 = ((size_t)cell * BATCH + b1) * HID + j;
    hn[o0] = h0v; hn[o1] = h1v;
    cn[o0] = c0;  cn[o1] = c1;
}

// -------------------- launch --------------------
extern "C" void kernel_launch(void* const* d_in, const int* in_sizes, int n_in,
                              void* d_out, int out_size)
{
    (void)in_sizes; (void)n_in; (void)out_size;
    const float* x     = (const float*)d_in[0];
    const float* w_ih  = (const float*)d_in[1];
    const float* w_hh  = (const float*)d_in[2];
    const float* b_ih  = (const float*)d_in[3];
    const float* b_hh  = (const float*)d_in[4];
    const float* a_ih  = (const float*)d_in[5];
    const float* bl_ih = (const float*)d_in[6];
    const float* a_hh  = (const float*)d_in[7];
    const float* bl_hh = (const float*)d_in[8];
    float* out = (float*)d_out;

    cudaFuncSetAttribute(lstm_rec, cudaFuncAttributeMaxDynamicSharedMemorySize, SMEM_REC);
    cudaFuncSetAttribute(gemm_gx_mma, cudaFuncAttributeMaxDynamicSharedMemorySize, SMEM_GEMM);

    size_t tih = (size_t)NC * G * INP;
    prep_weff_ih<<<(unsigned)((tih + 255) / 256), 256>>>(w_ih, a_ih, bl_ih);
    size_t thh = (size_t)NC * G * HID;
    prep_weff_hh<<<(unsigned)((thh + 255) / 256), 256>>>(w_hh, a_hh, bl_hh);
    split_x<<<(unsigned)((size_t)MROWS * INP / 1024), 256>>>(x);
    reset_bar<<<1, 32>>>();

    // ---- layer 0 ----
    gemm_gx_mma<<<dim3(16, 128, 2), 256, SMEM_GEMM>>>(0, b_ih, b_hh);
    lstm_rec<<<128, 128, SMEM_REC>>>(0, out);

    // ---- layer 1 ----
    gemm_gx_mma<<<dim3(16, 128, 2), 256, SMEM_GEMM>>>(1, b_ih, b_hh);
    lstm_rec<<<128, 128, SMEM_REC>>>(1, out);
}